// round 11
// baseline (speedup 1.0000x reference)
#include <cuda_runtime.h>
#include <math.h>
#include <stdint.h>

#define HWPX 16384        // 128*128
#define EPSF 1e-5f

__device__ __forceinline__ float siluf(float v) { return v / (1.0f + __expf(-v)); }

__device__ __forceinline__ uint32_t smem_u32(const void* p) {
    uint32_t a;
    asm("{ .reg .u64 t; cvta.to.shared.u64 t, %1; cvt.u32.u64 %0, t; }" : "=r"(a) : "l"(p));
    return a;
}
__device__ __forceinline__ void bulk_store(void* gdst, uint32_t ssrc, uint32_t bytes) {
    asm volatile("cp.async.bulk.global.shared::cta.bulk_group [%0], [%1], %2;"
                 :: "l"(gdst), "r"(ssrc), "r"(bytes) : "memory");
}
__device__ __forceinline__ void bulk_commit() {
    asm volatile("cp.async.bulk.commit_group;" ::: "memory");
}
template <int N>
__device__ __forceinline__ void bulk_wait() {
    asm volatile("cp.async.bulk.wait_group %0;" :: "n"(N) : "memory");
}
__device__ __forceinline__ void fence_async() {
    asm volatile("fence.proxy.async.shared::cta;" ::: "memory");
}

// One block per bg-group (128 blocks, 512 threads). R6 structure (pipelined LDG
// streaming, full L2 reuse). Phase C stores go smem -> TMA bulk stores, removing
// the 12-cyc/STG.128 LSU issue floor (one-thread bulk issue instead).
__global__ __launch_bounds__(512, 1)
void mega(const float* __restrict__ x,
          const float* __restrict__ w1, const float* __restrict__ b1,
          const float* __restrict__ w3, const float* __restrict__ b3,
          const float* __restrict__ gnw, const float* __restrict__ gnb,
          float* __restrict__ out)
{
    extern __shared__ float sm[];
    float* s1  = sm;               // [16][256]  silu(hw1): [c][i<128]=h-side, [c][128+j]=w-side
    float* s2  = sm + 4096;        // [16][256]
    float* hwb = sm + 8192;        // [16][258]  means+halo; aliased as h^2 tables after kA
    float* sq1 = sm + 8192;        // [16][128]
    float* sq2 = sm + 8192 + 2048; // [16][128]
    float* bufA = sm + 12320;      // staging: 8 ch x 16 rows x 128 cols = 16384 floats (64 KB)
    float* bufB = sm + 28704;      // same, channels 8-15

    __shared__ float w1s[256], w3s[768], b1s[16], b3s[16];
    __shared__ float statv[64], k1s[16], k2s[16], cpart[16], gbsh[16];
    __shared__ float Csm;

    const int bg   = blockIdx.x;
    const int tid  = threadIdx.x;
    const int lane = tid & 31;
    const int wid  = tid >> 5;                   // 0..15 : one warp per channel
    const float* xb = x   + (size_t)bg * 16 * HWPX;
    float*       ob = out + (size_t)bg * 16 * HWPX;

    // ---- stage tiny weights ----
    if (tid < 256) w1s[tid] = __ldg(w1 + tid);
    for (int i2 = tid; i2 < 768; i2 += 512) w3s[i2] = __ldg(w3 + i2 * 3 + 1); // kw=1 column
    if (tid < 16) { b1s[tid] = __ldg(b1 + tid); b3s[tid] = __ldg(b3 + tid); gbsh[tid] = __ldg(gnb + tid); }

    // ================= P1: row means + col means (pipelined, ascending) =================
    {
        const int c = wid;
        const float* g = xb + c * HWPX;
        float* hwc = hwb + c * 258;
        float4 cs = make_float4(0.f, 0.f, 0.f, 0.f);
        float4 va[8], vb[8];

        #pragma unroll
        for (int k = 0; k < 8; k++) va[k] = __ldg((const float4*)(g + k * 128) + lane);

        #pragma unroll 1
        for (int i0 = 0; i0 < 128; i0 += 16) {
            #pragma unroll
            for (int k = 0; k < 8; k++) vb[k] = __ldg((const float4*)(g + (i0 + 8 + k) * 128) + lane);
            {
                float r[8];
                #pragma unroll
                for (int k = 0; k < 8; k++) {
                    cs.x += va[k].x; cs.y += va[k].y; cs.z += va[k].z; cs.w += va[k].w;
                    r[k] = (va[k].x + va[k].y) + (va[k].z + va[k].w);
                }
                #pragma unroll
                for (int off = 16; off; off >>= 1) {
                    #pragma unroll
                    for (int k = 0; k < 8; k++) r[k] += __shfl_down_sync(0xffffffffu, r[k], off);
                }
                if (lane == 0) {
                    #pragma unroll
                    for (int k = 0; k < 8; k++) hwc[1 + i0 + k] = r[k] * (1.f / 128.f);
                }
            }
            if (i0 + 16 < 128) {
                #pragma unroll
                for (int k = 0; k < 8; k++) va[k] = __ldg((const float4*)(g + (i0 + 16 + k) * 128) + lane);
            }
            {
                float r[8];
                #pragma unroll
                for (int k = 0; k < 8; k++) {
                    cs.x += vb[k].x; cs.y += vb[k].y; cs.z += vb[k].z; cs.w += vb[k].w;
                    r[k] = (vb[k].x + vb[k].y) + (vb[k].z + vb[k].w);
                }
                #pragma unroll
                for (int off = 16; off; off >>= 1) {
                    #pragma unroll
                    for (int k = 0; k < 8; k++) r[k] += __shfl_down_sync(0xffffffffu, r[k], off);
                }
                if (lane == 0) {
                    #pragma unroll
                    for (int k = 0; k < 8; k++) hwc[1 + i0 + 8 + k] = r[k] * (1.f / 128.f);
                }
            }
        }
        hwc[129 + 4 * lane + 0] = cs.x * (1.f / 128.f);
        hwc[129 + 4 * lane + 1] = cs.y * (1.f / 128.f);
        hwc[129 + 4 * lane + 2] = cs.z * (1.f / 128.f);
        hwc[129 + 4 * lane + 3] = cs.w * (1.f / 128.f);
        if (lane == 0) { hwc[0] = 0.f; hwc[257] = 0.f; }
    }
    __syncthreads();

    // ================= kA: channel mix over concat length 256 =================
    for (int idx = tid; idx < 4096; idx += 512) {
        const int o = idx >> 8, l = idx & 255;
        float a1 = b1s[o], a2 = b3s[o];
        #pragma unroll
        for (int i = 0; i < 16; i++) {
            const float* h = hwb + i * 258 + l;
            const float h0 = h[0], h1 = h[1], h2 = h[2];
            a1 = fmaf(w1s[o * 16 + i], h1, a1);
            const int wb = (o * 16 + i) * 3;
            a2 = fmaf(w3s[wb], h0, fmaf(w3s[wb + 1], h1, fmaf(w3s[wb + 2], h2, a2)));
        }
        s1[o * 256 + l] = siluf(a1);
        s2[o * 256 + l] = siluf(a2);
    }
    __syncthreads();

    // ---- h^2 tables for the separable Q sums (into dead hwb region) ----
    for (int idx = tid; idx < 2048; idx += 512) {
        const int c = idx >> 7, i = idx & 127;
        const float a = s1[c * 256 + i];
        const float b = s2[c * 256 + i];
        sq1[idx] = a * a;
        sq2[idx] = b * b;
    }
    __syncthreads();

    // ================= P2: separable moment sums (pipelined, descending) =================
    {
        const int c = wid;
        const float* g = xb + c * HWPX;
        const float4 wa = *(const float4*)(s1 + c * 256 + 128 + 4 * lane);
        const float4 wb = *(const float4*)(s2 + c * 256 + 128 + 4 * lane);
        float4 wa2, wb2;
        wa2.x = wa.x * wa.x; wa2.y = wa.y * wa.y; wa2.z = wa.z * wa.z; wa2.w = wa.w * wa.w;
        wb2.x = wb.x * wb.x; wb2.y = wb.y * wb.y; wb2.z = wb.z * wb.z; wb2.w = wb.w * wb.w;
        float sa = 0.f, qa = 0.f, sb = 0.f, qb = 0.f;
        float4 va[8], vb[8];

        #pragma unroll
        for (int k = 0; k < 8; k++) va[k] = __ldg((const float4*)(g + (120 + k) * 128) + lane);

        #define P2_BODY(BUF, IBASE)                                                         \
        {                                                                                   \
            _Pragma("unroll")                                                               \
            for (int k = 0; k < 8; k++) {                                                   \
                const int i = (IBASE) + k;                                                  \
                const float h1  = s1[c * 256 + i];                                          \
                const float h2  = s2[c * 256 + i];                                          \
                const float h1q = sq1[c * 128 + i];                                         \
                const float h2q = sq2[c * 128 + i];                                         \
                const float v2x = BUF[k].x * BUF[k].x, v2y = BUF[k].y * BUF[k].y;           \
                const float v2z = BUF[k].z * BUF[k].z, v2w = BUF[k].w * BUF[k].w;           \
                float d1 = BUF[k].x * wa.x;                                                 \
                d1 = fmaf(BUF[k].y, wa.y, d1); d1 = fmaf(BUF[k].z, wa.z, d1);               \
                d1 = fmaf(BUF[k].w, wa.w, d1);                                              \
                float e1 = v2x * wa2.x;                                                     \
                e1 = fmaf(v2y, wa2.y, e1); e1 = fmaf(v2z, wa2.z, e1);                       \
                e1 = fmaf(v2w, wa2.w, e1);                                                  \
                sa = fmaf(h1, d1, sa);                                                      \
                qa = fmaf(h1q, e1, qa);                                                     \
                float d2 = BUF[k].x * wb.x;                                                 \
                d2 = fmaf(BUF[k].y, wb.y, d2); d2 = fmaf(BUF[k].z, wb.z, d2);               \
                d2 = fmaf(BUF[k].w, wb.w, d2);                                              \
                float e2 = v2x * wb2.x;                                                     \
                e2 = fmaf(v2y, wb2.y, e2); e2 = fmaf(v2z, wb2.z, e2);                       \
                e2 = fmaf(v2w, wb2.w, e2);                                                  \
                sb = fmaf(h2, d2, sb);                                                      \
                qb = fmaf(h2q, e2, qb);                                                     \
            }                                                                               \
        }

        #pragma unroll 1
        for (int i0 = 120; i0 >= 0; i0 -= 16) {
            #pragma unroll
            for (int k = 0; k < 8; k++) vb[k] = __ldg((const float4*)(g + (i0 - 8 + k) * 128) + lane);
            P2_BODY(va, i0)
            if (i0 - 16 >= 0) {
                #pragma unroll
                for (int k = 0; k < 8; k++) va[k] = __ldg((const float4*)(g + (i0 - 16 + k) * 128) + lane);
            }
            P2_BODY(vb, i0 - 8)
        }
        #undef P2_BODY

        #pragma unroll
        for (int off = 16; off; off >>= 1) {
            sa += __shfl_down_sync(0xffffffffu, sa, off);
            qa += __shfl_down_sync(0xffffffffu, qa, off);
            sb += __shfl_down_sync(0xffffffffu, sb, off);
            qb += __shfl_down_sync(0xffffffffu, qb, off);
        }
        if (lane == 0) { statv[c * 4] = sa; statv[c * 4 + 1] = qa; statv[c * 4 + 2] = sb; statv[c * 4 + 3] = qb; }
    }
    __syncthreads();

    // ================= kB: scalars =================
    if (tid < 16) {
        float m = -1e30f;
        #pragma unroll
        for (int i = 0; i < 16; i++) m = fmaxf(m, gbsh[i]);
        float se = 0.f;
        #pragma unroll
        for (int i = 0; i < 16; i++) se += __expf(gbsh[i] - m);
        const float a = __expf(gbsh[tid] - m) / se;        // a1 == a2 == softmax(gn_b)
        const float S1 = statv[tid * 4], Q1 = statv[tid * 4 + 1];
        const float S2 = statv[tid * 4 + 2], Q2 = statv[tid * 4 + 3];
        const float mu1 = S1 * (1.f / 16384.f);
        const float r1  = rsqrtf(Q1 * (1.f / 16384.f) - mu1 * mu1 + EPSF);
        const float mu2 = S2 * (1.f / 16384.f);
        const float r2  = rsqrtf(Q2 * (1.f / 16384.f) - mu2 * mu2 + EPSF);
        const float gw = __ldg(gnw + tid);
        k1s[tid] = a * gw * r1;
        k2s[tid] = a * gw * r2;
        cpart[tid] = a * (2.f * gbsh[tid] - gw * (mu1 * r1 + mu2 * r2));
    }
    __syncthreads();
    if (tid == 0) {
        float s = 0.f;
        #pragma unroll
        for (int i = 0; i < 16; i++) s += cpart[i];
        Csm = s;
    }
    // fold k1/k2 into the i-side silu tables (j-side stays unscaled)
    for (int idx = tid; idx < 2048; idx += 512) {
        const int c = idx >> 7, i = idx & 127;
        s1[c * 256 + i] *= k1s[c];
        s2[c * 256 + i] *= k2s[c];
    }
    __syncthreads();

    // ================= C: wts + gate; output via smem -> TMA bulk stores =================
    {
        const int rloc = tid >> 5;                     // 0..15 rows per slab
        const float Cc = Csm;
        const uint32_t sbufA = smem_u32(bufA);
        const uint32_t sbufB = smem_u32(bufB);

        #pragma unroll 1
        for (int s = 0; s < 8; s++) {
            const int i = s * 16 + rloc;
            float4 v[16];
            float4 w4 = make_float4(Cc, Cc, Cc, Cc);
            #pragma unroll
            for (int c = 0; c < 16; c++) {
                v[c] = __ldcs((const float4*)(xb + c * HWPX + i * 128) + lane);
                const float a1 = s1[c * 256 + i];
                const float a2 = s2[c * 256 + i];
                const float4 j1 = *(const float4*)(s1 + c * 256 + 128 + 4 * lane);
                const float4 j2 = *(const float4*)(s2 + c * 256 + 128 + 4 * lane);
                w4.x += v[c].x * fmaf(a1, j1.x, a2 * j2.x);
                w4.y += v[c].y * fmaf(a1, j1.y, a2 * j2.y);
                w4.z += v[c].z * fmaf(a1, j1.z, a2 * j2.z);
                w4.w += v[c].w * fmaf(a1, j1.w, a2 * j2.w);
            }
            float4 sw;
            sw.x = siluf(w4.x); sw.y = siluf(w4.y); sw.z = siluf(w4.z); sw.w = siluf(w4.w);

            // ---- channels 0-7 -> bufA ----
            if (s > 0) {                                // A_{s-1} must be drained
                if (tid == 0) bulk_wait<1>();
                __syncthreads();
            }
            #pragma unroll
            for (int c = 0; c < 8; c++) {
                float4 o4;
                o4.x = v[c].x * sw.x; o4.y = v[c].y * sw.y;
                o4.z = v[c].z * sw.z; o4.w = v[c].w * sw.w;
                *(float4*)(bufA + c * 2048 + rloc * 128 + 4 * lane) = o4;
            }
            __syncthreads();
            if (tid == 0) {
                fence_async();
                #pragma unroll
                for (int c = 0; c < 8; c++)
                    bulk_store(ob + c * HWPX + s * 16 * 128, sbufA + c * 8192, 8192);
                bulk_commit();                          // group A_s
                bulk_wait<1>();                         // B_{s-1} drained -> bufB free
            }
            __syncthreads();

            // ---- channels 8-15 -> bufB ----
            #pragma unroll
            for (int c = 8; c < 16; c++) {
                float4 o4;
                o4.x = v[c].x * sw.x; o4.y = v[c].y * sw.y;
                o4.z = v[c].z * sw.z; o4.w = v[c].w * sw.w;
                *(float4*)(bufB + (c - 8) * 2048 + rloc * 128 + 4 * lane) = o4;
            }
            __syncthreads();
            if (tid == 0) {
                fence_async();
                #pragma unroll
                for (int c = 8; c < 16; c++)
                    bulk_store(ob + c * HWPX + s * 16 * 128, sbufB + (c - 8) * 8192, 8192);
                bulk_commit();                          // group B_s
            }
        }
        if (tid == 0) bulk_wait<0>();                   // drain before exit
        __syncthreads();
    }
}

// ---------------- launch ----------------
extern "C" void kernel_launch(void* const* d_in, const int* in_sizes, int n_in,
                              void* d_out, int out_size) {
    const float* x    = (const float*)d_in[0];
    const float* w1   = (const float*)d_in[1];
    const float* b1   = (const float*)d_in[2];
    const float* w3   = (const float*)d_in[3];
    const float* b3   = (const float*)d_in[4];
    const float* gn_w = (const float*)d_in[5];
    const float* gn_b = (const float*)d_in[6];
    float* out = (float*)d_out;

    // s1 4096 + s2 4096 + hwb 4128 + staging 32768 = 45088 floats = 180352 B
    const int smem_bytes = 45088 * (int)sizeof(float);
    static bool attr_done = false;
    if (!attr_done) {
        cudaFuncSetAttribute(mega, cudaFuncAttributeMaxDynamicSharedMemorySize, smem_bytes);
        attr_done = true;
    }
    mega<<<128, 512, smem_bytes>>>(x, w1, b1, w3, b3, gn_w, gn_b, out);
}

// round 12
// speedup vs baseline: 1.0889x; 1.0889x over previous
#include <cuda_runtime.h>
#include <math.h>
#include <stdint.h>

#define HWPX 16384          // 128*128 floats per image
#define CHUNK_FLOATS 8192   // 32 KB chunk = half a channel image (64 rows)
#define CHUNK_BYTES 32768
#define EPSF 1e-5f

__device__ __forceinline__ float siluf(float v) { return v / (1.0f + __expf(-v)); }

__device__ __forceinline__ uint32_t smem_u32(const void* p) {
    uint32_t a;
    asm("{ .reg .u64 t; cvta.to.shared.u64 t, %1; cvt.u32.u64 %0, t; }" : "=r"(a) : "l"(p));
    return a;
}
__device__ __forceinline__ void mbar_init(uint32_t a, uint32_t count) {
    asm volatile("mbarrier.init.shared.b64 [%0], %1;" :: "r"(a), "r"(count) : "memory");
}
__device__ __forceinline__ void mbar_expect_tx(uint32_t a, uint32_t bytes) {
    asm volatile("mbarrier.arrive.expect_tx.shared.b64 _, [%0], %1;" :: "r"(a), "r"(bytes) : "memory");
}
__device__ __forceinline__ void mbar_wait(uint32_t a, uint32_t parity) {
    asm volatile(
        "{\n\t.reg .pred P;\n\t"
        "WAIT_%=:\n\t"
        "mbarrier.try_wait.parity.acquire.cta.shared::cta.b64 P, [%0], %1, 0x989680;\n\t"
        "@!P bra WAIT_%=;\n\t"
        "}" :: "r"(a), "r"(parity) : "memory");
}
__device__ __forceinline__ void bulk_load(uint32_t dst, const void* src, uint32_t bytes, uint32_t mbar) {
    asm volatile(
        "cp.async.bulk.shared::cluster.global.mbarrier::complete_tx::bytes [%0], [%1], %2, [%3];"
        :: "r"(dst), "l"(src), "r"(bytes), "r"(mbar) : "memory");
}

// One block per bg-group (128 blocks, 512 threads). P1/P2 stream x via a
// 4 x 32KB TMA ring (depth-3 outstanding during every compute window).
// Chunk schedule: g=0..31 ascending (P1), g=32..63 -> addresses 31..0 (P2,
// descending = L2-LRU-optimal). C reads ascending from ch0 (P2's warm tail).
__global__ __launch_bounds__(512, 1)
void mega(const float* __restrict__ x,
          const float* __restrict__ w1, const float* __restrict__ b1,
          const float* __restrict__ w3, const float* __restrict__ b3,
          const float* __restrict__ gnw, const float* __restrict__ gnb,
          float* __restrict__ out)
{
    extern __shared__ float sm[];
    float* stage = sm;                 // 4 x 8192 floats (4 x 32 KB ring)
    float* s1    = sm + 32768;         // [16][256]
    float* s2    = sm + 36864;         // [16][256]
    float* hwb   = sm + 40960;         // [16][258] means+halo; aliased post-kA
    float* sq1   = hwb;                // [16][128]
    float* sq2   = hwb + 2048;         // [16][128]
    float* colp  = sm + 45088;         // [16 warps][128] column partials

    __shared__ __align__(8) uint64_t mb[4];
    __shared__ float w1s[256], w3s[768], b1s[16], b3s[16], gbsh[16];
    __shared__ float statv[64], k1s[16], k2s[16], cpart[16];
    __shared__ float red[16][4];
    __shared__ float Csm;

    const int bg   = blockIdx.x;
    const int tid  = threadIdx.x;
    const int lane = tid & 31;
    const int w    = tid >> 5;                    // 0..15
    const float* xb = x   + (size_t)bg * 16 * HWPX;
    float*       ob = out + (size_t)bg * 16 * HWPX;
    const uint32_t stage0 = smem_u32(stage);

    // ---- stage tiny weights ----
    if (tid < 256) w1s[tid] = __ldg(w1 + tid);
    for (int i2 = tid; i2 < 768; i2 += 512) w3s[i2] = __ldg(w3 + i2 * 3 + 1); // kw=1 col
    if (tid < 16) { b1s[tid] = __ldg(b1 + tid); b3s[tid] = __ldg(b3 + tid); gbsh[tid] = __ldg(gnb + tid); }

    if (tid == 0) {
        #pragma unroll
        for (int i = 0; i < 4; i++) mbar_init(smem_u32(&mb[i]), 1);
    }
    __syncthreads();

    // initial prefetch: chunks 0..3
    if (tid == 0) {
        #pragma unroll
        for (int g = 0; g < 4; g++) {
            const uint32_t m = smem_u32(&mb[g]);
            mbar_expect_tx(m, CHUNK_BYTES);
            bulk_load(stage0 + g * CHUNK_BYTES, xb + (size_t)g * CHUNK_FLOATS, CHUNK_BYTES, m);
        }
    }

    // ================= P1: row + col means (chunks 0..31, ascending) =================
    {
        float4 cs = make_float4(0.f, 0.f, 0.f, 0.f);   // per-warp col partial across pair
        #pragma unroll 1
        for (int g = 0; g < 32; g++) {
            const int buf = g & 3;
            mbar_wait(smem_u32(&mb[buf]), (g >> 2) & 1);
            const float* S = stage + buf * CHUNK_FLOATS;
            const int ch = g >> 1, half = g & 1;

            float r[4];
            #pragma unroll
            for (int t = 0; t < 4; t++) {
                const float4 v = *(const float4*)(S + (w * 4 + t) * 128 + 4 * lane);
                cs.x += v.x; cs.y += v.y; cs.z += v.z; cs.w += v.w;
                r[t] = (v.x + v.y) + (v.z + v.w);
            }
            #pragma unroll
            for (int off = 16; off; off >>= 1) {
                #pragma unroll
                for (int t = 0; t < 4; t++) r[t] += __shfl_down_sync(0xffffffffu, r[t], off);
            }
            if (lane == 0) {
                #pragma unroll
                for (int t = 0; t < 4; t++)
                    hwb[ch * 258 + 1 + half * 64 + w * 4 + t] = r[t] * (1.f / 128.f);
            }
            const bool chEnd = (half == 1);
            if (chEnd) *(float4*)(colp + w * 128 + 4 * lane) = cs;
            __syncthreads();                           // chunk consumed (+ colp visible)

            if (tid == 0 && g + 4 < 64) {              // unified prefetch (covers P2 32..35)
                const int gn = g + 4;
                const int cidx = (gn < 32) ? gn : (63 - gn);
                const uint32_t m = smem_u32(&mb[gn & 3]);
                mbar_expect_tx(m, CHUNK_BYTES);
                bulk_load(stage0 + (gn & 3) * CHUNK_BYTES,
                          xb + (size_t)cidx * CHUNK_FLOATS, CHUNK_BYTES, m);
            }
            if (chEnd) {
                if (tid < 128) {
                    float s = 0.f;
                    #pragma unroll
                    for (int ww = 0; ww < 16; ww++) s += colp[ww * 128 + tid];
                    hwb[ch * 258 + 129 + tid] = s * (1.f / 128.f);
                }
                cs = make_float4(0.f, 0.f, 0.f, 0.f);
            }
        }
    }
    if (tid < 16) { hwb[tid * 258] = 0.f; hwb[tid * 258 + 257] = 0.f; }   // conv halo
    __syncthreads();

    // ================= kA: channel mix over concat length 256 (P2 chunks land meanwhile) ====
    for (int idx = tid; idx < 4096; idx += 512) {
        const int o = idx >> 8, l = idx & 255;
        float a1 = b1s[o], a2 = b3s[o];
        #pragma unroll
        for (int i = 0; i < 16; i++) {
            const float* h = hwb + i * 258 + l;
            const float h0 = h[0], h1 = h[1], h2 = h[2];
            a1 = fmaf(w1s[o * 16 + i], h1, a1);
            const int wb = (o * 16 + i) * 3;
            a2 = fmaf(w3s[wb], h0, fmaf(w3s[wb + 1], h1, fmaf(w3s[wb + 2], h2, a2)));
        }
        s1[o * 256 + l] = siluf(a1);
        s2[o * 256 + l] = siluf(a2);
    }
    __syncthreads();
    for (int idx = tid; idx < 2048; idx += 512) {      // h^2 tables into dead hwb region
        const int c = idx >> 7, i = idx & 127;
        const float a = s1[c * 256 + i];
        const float b = s2[c * 256 + i];
        sq1[idx] = a * a;
        sq2[idx] = b * b;
    }
    __syncthreads();

    // ================= P2: separable moment sums (chunks 32..63 -> addr 31..0) ============
    {
        float sa = 0.f, qa = 0.f, sb = 0.f, qb = 0.f;
        float4 wa = make_float4(0.f,0.f,0.f,0.f), wb = wa, wa2 = wa, wb2 = wa;
        #pragma unroll 1
        for (int g = 32; g < 64; g++) {
            const int buf  = g & 3;
            const int cidx = 63 - g;                   // 31..0
            const int ch   = cidx >> 1, half = cidx & 1;   // per channel: half 1 then 0
            if (half == 1) {                           // pair start
                wa = *(const float4*)(s1 + ch * 256 + 128 + 4 * lane);
                wb = *(const float4*)(s2 + ch * 256 + 128 + 4 * lane);
                wa2.x = wa.x * wa.x; wa2.y = wa.y * wa.y; wa2.z = wa.z * wa.z; wa2.w = wa.w * wa.w;
                wb2.x = wb.x * wb.x; wb2.y = wb.y * wb.y; wb2.z = wb.z * wb.z; wb2.w = wb.w * wb.w;
                sa = qa = sb = qb = 0.f;
            }
            mbar_wait(smem_u32(&mb[buf]), (g >> 2) & 1);
            const float* S = stage + buf * CHUNK_FLOATS;

            #pragma unroll
            for (int t = 0; t < 4; t++) {
                const int r = w * 4 + t;
                const int i = half * 64 + r;
                const float4 v = *(const float4*)(S + r * 128 + 4 * lane);
                const float h1  = s1[ch * 256 + i];
                const float h2  = s2[ch * 256 + i];
                const float h1q = sq1[ch * 128 + i];
                const float h2q = sq2[ch * 128 + i];
                const float v2x = v.x * v.x, v2y = v.y * v.y, v2z = v.z * v.z, v2w = v.w * v.w;
                float d1 = v.x * wa.x;
                d1 = fmaf(v.y, wa.y, d1); d1 = fmaf(v.z, wa.z, d1); d1 = fmaf(v.w, wa.w, d1);
                float e1 = v2x * wa2.x;
                e1 = fmaf(v2y, wa2.y, e1); e1 = fmaf(v2z, wa2.z, e1); e1 = fmaf(v2w, wa2.w, e1);
                sa = fmaf(h1, d1, sa);
                qa = fmaf(h1q, e1, qa);
                float d2 = v.x * wb.x;
                d2 = fmaf(v.y, wb.y, d2); d2 = fmaf(v.z, wb.z, d2); d2 = fmaf(v.w, wb.w, d2);
                float e2 = v2x * wb2.x;
                e2 = fmaf(v2y, wb2.y, e2); e2 = fmaf(v2z, wb2.z, e2); e2 = fmaf(v2w, wb2.w, e2);
                sb = fmaf(h2, d2, sb);
                qb = fmaf(h2q, e2, qb);
            }
            __syncthreads();                           // chunk consumed

            if (tid == 0 && g + 4 < 64) {
                const int gn = g + 4;
                const int cx = 63 - gn;
                const uint32_t m = smem_u32(&mb[gn & 3]);
                mbar_expect_tx(m, CHUNK_BYTES);
                bulk_load(stage0 + (gn & 3) * CHUNK_BYTES,
                          xb + (size_t)cx * CHUNK_FLOATS, CHUNK_BYTES, m);
            }
            if (half == 0) {                           // pair end: reduce channel stats
                float ra = sa, rqa = qa, rb = sb, rqb = qb;
                #pragma unroll
                for (int off = 16; off; off >>= 1) {
                    ra  += __shfl_down_sync(0xffffffffu, ra, off);
                    rqa += __shfl_down_sync(0xffffffffu, rqa, off);
                    rb  += __shfl_down_sync(0xffffffffu, rb, off);
                    rqb += __shfl_down_sync(0xffffffffu, rqb, off);
                }
                if (lane == 0) { red[w][0] = ra; red[w][1] = rqa; red[w][2] = rb; red[w][3] = rqb; }
                __syncthreads();
                if (tid < 4) {
                    float s = 0.f;
                    #pragma unroll
                    for (int ww = 0; ww < 16; ww++) s += red[ww][tid];
                    statv[ch * 4 + tid] = s;
                }
            }
        }
    }
    __syncthreads();

    // ================= kB: scalars =================
    if (tid < 16) {
        float m = -1e30f;
        #pragma unroll
        for (int i = 0; i < 16; i++) m = fmaxf(m, gbsh[i]);
        float se = 0.f;
        #pragma unroll
        for (int i = 0; i < 16; i++) se += __expf(gbsh[i] - m);
        const float a = __expf(gbsh[tid] - m) / se;    // a1 == a2 == softmax(gn_b)
        const float S1 = statv[tid * 4], Q1 = statv[tid * 4 + 1];
        const float S2 = statv[tid * 4 + 2], Q2 = statv[tid * 4 + 3];
        const float mu1 = S1 * (1.f / 16384.f);
        const float r1  = rsqrtf(Q1 * (1.f / 16384.f) - mu1 * mu1 + EPSF);
        const float mu2 = S2 * (1.f / 16384.f);
        const float r2  = rsqrtf(Q2 * (1.f / 16384.f) - mu2 * mu2 + EPSF);
        const float gw = __ldg(gnw + tid);
        k1s[tid] = a * gw * r1;
        k2s[tid] = a * gw * r2;
        cpart[tid] = a * (2.f * gbsh[tid] - gw * (mu1 * r1 + mu2 * r2));
    }
    __syncthreads();
    if (tid == 0) {
        float s = 0.f;
        #pragma unroll
        for (int i = 0; i < 16; i++) s += cpart[i];
        Csm = s;
    }
    for (int idx = tid; idx < 2048; idx += 512) {      // fold k into i-side tables
        const int c = idx >> 7, i = idx & 127;
        s1[c * 256 + i] *= k1s[c];
        s2[c * 256 + i] *= k2s[c];
    }
    __syncthreads();

    // ================= C: wts + gate + output (ascending rows, x read once) =================
    {
        const int rloc = tid >> 5;                     // 0..15
        const float Cc = Csm;
        #pragma unroll 1
        for (int s = 0; s < 8; s++) {
            const int i = s * 16 + rloc;
            float4 v[16];
            float4 w4 = make_float4(Cc, Cc, Cc, Cc);
            #pragma unroll
            for (int c = 0; c < 16; c++) {
                v[c] = __ldcs((const float4*)(xb + c * HWPX + i * 128) + lane);
                const float a1 = s1[c * 256 + i];
                const float a2 = s2[c * 256 + i];
                const float4 j1 = *(const float4*)(s1 + c * 256 + 128 + 4 * lane);
                const float4 j2 = *(const float4*)(s2 + c * 256 + 128 + 4 * lane);
                w4.x += v[c].x * fmaf(a1, j1.x, a2 * j2.x);
                w4.y += v[c].y * fmaf(a1, j1.y, a2 * j2.y);
                w4.z += v[c].z * fmaf(a1, j1.z, a2 * j2.z);
                w4.w += v[c].w * fmaf(a1, j1.w, a2 * j2.w);
            }
            float4 sw;
            sw.x = siluf(w4.x); sw.y = siluf(w4.y); sw.z = siluf(w4.z); sw.w = siluf(w4.w);
            #pragma unroll
            for (int c = 0; c < 16; c++) {
                float4 o4;
                o4.x = v[c].x * sw.x; o4.y = v[c].y * sw.y;
                o4.z = v[c].z * sw.z; o4.w = v[c].w * sw.w;
                __stcs((float4*)(ob + c * HWPX + i * 128) + lane, o4);
            }
        }
    }
}

// ---------------- launch ----------------
extern "C" void kernel_launch(void* const* d_in, const int* in_sizes, int n_in,
                              void* d_out, int out_size) {
    const float* x    = (const float*)d_in[0];
    const float* w1   = (const float*)d_in[1];
    const float* b1   = (const float*)d_in[2];
    const float* w3   = (const float*)d_in[3];
    const float* b3   = (const float*)d_in[4];
    const float* gn_w = (const float*)d_in[5];
    const float* gn_b = (const float*)d_in[6];
    float* out = (float*)d_out;

    // stage 32768 + s1 4096 + s2 4096 + hwb 4128 + colp 2048 = 47136 floats
    const int smem_bytes = 47136 * (int)sizeof(float);   // 188544 B
    static bool attr_done = false;
    if (!attr_done) {
        cudaFuncSetAttribute(mega, cudaFuncAttributeMaxDynamicSharedMemorySize, smem_bytes);
        attr_done = true;
    }
    mega<<<128, 512, smem_bytes>>>(x, w1, b1, w3, b3, gn_w, gn_b, out);
}

// round 14
// speedup vs baseline: 1.1391x; 1.0461x over previous
#include <cuda_runtime.h>
#include <math.h>
#include <stdint.h>

#define HWPX 16384        // 128*128
#define EPSF 1e-5f

__device__ __forceinline__ float siluf(float v) { return v / (1.0f + __expf(-v)); }

// 256-bit cold read with L2 evict-last hint (ptxas requires v4.b64 width for the hint)
__device__ __forceinline__ void ldg_el8(const float* p, float* v) {
    unsigned long long a, b, c, d;
    asm volatile("ld.global.nc.L2::evict_last.v4.b64 {%0,%1,%2,%3}, [%4];"
                 : "=l"(a), "=l"(b), "=l"(c), "=l"(d) : "l"(p));
    v[0] = __uint_as_float((unsigned)a); v[1] = __uint_as_float((unsigned)(a >> 32));
    v[2] = __uint_as_float((unsigned)b); v[3] = __uint_as_float((unsigned)(b >> 32));
    v[4] = __uint_as_float((unsigned)c); v[5] = __uint_as_float((unsigned)(c >> 32));
    v[6] = __uint_as_float((unsigned)d); v[7] = __uint_as_float((unsigned)(d >> 32));
}

// One block per bg-group (128 blocks, 512 threads). R6 structure; P1 uses
// 256-bit evict_last loads to pin x in L2 for P2 (descending, warm) and C.
__global__ __launch_bounds__(512, 1)
void mega(const float* __restrict__ x,
          const float* __restrict__ w1, const float* __restrict__ b1,
          const float* __restrict__ w3, const float* __restrict__ b3,
          const float* __restrict__ gnw, const float* __restrict__ gnb,
          float* __restrict__ out)
{
    extern __shared__ float sm[];
    float* s1  = sm;               // [16][256]
    float* s2  = sm + 4096;        // [16][256]
    float* hwb = sm + 8192;        // [16][258]  means+halo; aliased as h^2 tables after kA
    float* sq1 = sm + 8192;        // [16][128]
    float* sq2 = sm + 8192 + 2048; // [16][128]

    __shared__ float w1s[256], w3s[768], b1s[16], b3s[16];
    __shared__ float statv[64], k1s[16], k2s[16], cpart[16], gbsh[16];
    __shared__ float Csm;

    const int bg   = blockIdx.x;
    const int tid  = threadIdx.x;
    const int lane = tid & 31;
    const int wid  = tid >> 5;                   // 0..15 : one warp per channel
    const float* xb = x   + (size_t)bg * 16 * HWPX;
    float*       ob = out + (size_t)bg * 16 * HWPX;

    // ---- stage tiny weights ----
    if (tid < 256) w1s[tid] = __ldg(w1 + tid);
    for (int i2 = tid; i2 < 768; i2 += 512) w3s[i2] = __ldg(w3 + i2 * 3 + 1); // kw=1 column
    if (tid < 16) { b1s[tid] = __ldg(b1 + tid); b3s[tid] = __ldg(b3 + tid); gbsh[tid] = __ldg(gnb + tid); }

    // ================= P1: row + col means (pipelined, ascending, 256-bit evict_last) =====
    {
        const int c = wid;
        const float* g = xb + c * HWPX;
        float* hwc = hwb + c * 258;
        const int half = lane >> 4;              // 0/1: which of 2 rows per load group
        const int seg  = lane & 15;              // 8-float column segment
        const int colbase = seg * 8;
        float cs[8];
        #pragma unroll
        for (int j = 0; j < 8; j++) cs[j] = 0.f;
        float va[4][8], vb[4][8];

        #define P1_LOAD(BUF, I0)                                                   \
        {                                                                          \
            _Pragma("unroll")                                                      \
            for (int k = 0; k < 4; k++)                                            \
                ldg_el8(g + ((I0) + 2 * k + half) * 128 + colbase, BUF[k]);        \
        }
        #define P1_BODY(BUF, I0)                                                   \
        {                                                                          \
            _Pragma("unroll")                                                      \
            for (int k = 0; k < 4; k++) {                                          \
                float r = 0.f;                                                     \
                _Pragma("unroll")                                                  \
                for (int j = 0; j < 8; j++) { cs[j] += BUF[k][j]; r += BUF[k][j]; }\
                r += __shfl_xor_sync(0xffffffffu, r, 1);                           \
                r += __shfl_xor_sync(0xffffffffu, r, 2);                           \
                r += __shfl_xor_sync(0xffffffffu, r, 4);                           \
                r += __shfl_xor_sync(0xffffffffu, r, 8);                           \
                if (seg == 0) hwc[1 + (I0) + 2 * k + half] = r * (1.f / 128.f);    \
            }                                                                      \
        }

        P1_LOAD(va, 0)
        #pragma unroll 1
        for (int i0 = 0; i0 < 128; i0 += 16) {
            P1_LOAD(vb, i0 + 8)
            P1_BODY(va, i0)
            if (i0 + 16 < 128) P1_LOAD(va, i0 + 16)
            P1_BODY(vb, i0 + 8)
        }
        #undef P1_LOAD
        #undef P1_BODY

        #pragma unroll
        for (int j = 0; j < 8; j++) cs[j] += __shfl_xor_sync(0xffffffffu, cs[j], 16);
        if (half == 0) {
            #pragma unroll
            for (int j = 0; j < 8; j++)
                hwc[129 + colbase + j] = cs[j] * (1.f / 128.f);
        }
        if (lane == 0) { hwc[0] = 0.f; hwc[257] = 0.f; }   // conv halo (zero padding)
    }
    __syncthreads();

    // ================= kA: channel mix over concat length 256 =================
    for (int idx = tid; idx < 4096; idx += 512) {
        const int o = idx >> 8, l = idx & 255;
        float a1 = b1s[o], a2 = b3s[o];
        #pragma unroll
        for (int i = 0; i < 16; i++) {
            const float* h = hwb + i * 258 + l;
            const float h0 = h[0], h1 = h[1], h2 = h[2];
            a1 = fmaf(w1s[o * 16 + i], h1, a1);
            const int wb = (o * 16 + i) * 3;
            a2 = fmaf(w3s[wb], h0, fmaf(w3s[wb + 1], h1, fmaf(w3s[wb + 2], h2, a2)));
        }
        s1[o * 256 + l] = siluf(a1);
        s2[o * 256 + l] = siluf(a2);
    }
    __syncthreads();

    // ---- h^2 tables for the separable Q sums (into dead hwb region) ----
    for (int idx = tid; idx < 2048; idx += 512) {
        const int c = idx >> 7, i = idx & 127;
        const float a = s1[c * 256 + i];
        const float b = s2[c * 256 + i];
        sq1[idx] = a * a;
        sq2[idx] = b * b;
    }
    __syncthreads();

    // ================= P2: separable moment sums (pipelined, descending, L2-warm) ========
    {
        const int c = wid;
        const float* g = xb + c * HWPX;
        const float4 wa = *(const float4*)(s1 + c * 256 + 128 + 4 * lane);
        const float4 wb = *(const float4*)(s2 + c * 256 + 128 + 4 * lane);
        float4 wa2, wb2;
        wa2.x = wa.x * wa.x; wa2.y = wa.y * wa.y; wa2.z = wa.z * wa.z; wa2.w = wa.w * wa.w;
        wb2.x = wb.x * wb.x; wb2.y = wb.y * wb.y; wb2.z = wb.z * wb.z; wb2.w = wb.w * wb.w;
        float sa = 0.f, qa = 0.f, sb = 0.f, qb = 0.f;
        float4 va[8], vb[8];

        #pragma unroll
        for (int k = 0; k < 8; k++) va[k] = __ldg((const float4*)(g + (120 + k) * 128) + lane);

        #define P2_BODY(BUF, IBASE)                                                         \
        {                                                                                   \
            _Pragma("unroll")                                                               \
            for (int k = 0; k < 8; k++) {                                                   \
                const int i = (IBASE) + k;                                                  \
                const float h1  = s1[c * 256 + i];                                          \
                const float h2  = s2[c * 256 + i];                                          \
                const float h1q = sq1[c * 128 + i];                                         \
                const float h2q = sq2[c * 128 + i];                                         \
                const float v2x = BUF[k].x * BUF[k].x, v2y = BUF[k].y * BUF[k].y;           \
                const float v2z = BUF[k].z * BUF[k].z, v2w = BUF[k].w * BUF[k].w;           \
                float d1 = BUF[k].x * wa.x;                                                 \
                d1 = fmaf(BUF[k].y, wa.y, d1); d1 = fmaf(BUF[k].z, wa.z, d1);               \
                d1 = fmaf(BUF[k].w, wa.w, d1);                                              \
                float e1 = v2x * wa2.x;                                                     \
                e1 = fmaf(v2y, wa2.y, e1); e1 = fmaf(v2z, wa2.z, e1);                       \
                e1 = fmaf(v2w, wa2.w, e1);                                                  \
                sa = fmaf(h1, d1, sa);                                                      \
                qa = fmaf(h1q, e1, qa);                                                     \
                float d2 = BUF[k].x * wb.x;                                                 \
                d2 = fmaf(BUF[k].y, wb.y, d2); d2 = fmaf(BUF[k].z, wb.z, d2);               \
                d2 = fmaf(BUF[k].w, wb.w, d2);                                              \
                float e2 = v2x * wb2.x;                                                     \
                e2 = fmaf(v2y, wb2.y, e2); e2 = fmaf(v2z, wb2.z, e2);                       \
                e2 = fmaf(v2w, wb2.w, e2);                                                  \
                sb = fmaf(h2, d2, sb);                                                      \
                qb = fmaf(h2q, e2, qb);                                                     \
            }                                                                               \
        }

        #pragma unroll 1
        for (int i0 = 120; i0 >= 0; i0 -= 16) {
            #pragma unroll
            for (int k = 0; k < 8; k++) vb[k] = __ldg((const float4*)(g + (i0 - 8 + k) * 128) + lane);
            P2_BODY(va, i0)
            if (i0 - 16 >= 0) {
                #pragma unroll
                for (int k = 0; k < 8; k++) va[k] = __ldg((const float4*)(g + (i0 - 16 + k) * 128) + lane);
            }
            P2_BODY(vb, i0 - 8)
        }
        #undef P2_BODY

        #pragma unroll
        for (int off = 16; off; off >>= 1) {
            sa += __shfl_down_sync(0xffffffffu, sa, off);
            qa += __shfl_down_sync(0xffffffffu, qa, off);
            sb += __shfl_down_sync(0xffffffffu, sb, off);
            qb += __shfl_down_sync(0xffffffffu, qb, off);
        }
        if (lane == 0) { statv[c * 4] = sa; statv[c * 4 + 1] = qa; statv[c * 4 + 2] = sb; statv[c * 4 + 3] = qb; }
    }
    __syncthreads();

    // ================= kB: scalars =================
    if (tid < 16) {
        float m = -1e30f;
        #pragma unroll
        for (int i = 0; i < 16; i++) m = fmaxf(m, gbsh[i]);
        float se = 0.f;
        #pragma unroll
        for (int i = 0; i < 16; i++) se += __expf(gbsh[i] - m);
        const float a = __expf(gbsh[tid] - m) / se;        // a1 == a2 == softmax(gn_b)
        const float S1 = statv[tid * 4], Q1 = statv[tid * 4 + 1];
        const float S2 = statv[tid * 4 + 2], Q2 = statv[tid * 4 + 3];
        const float mu1 = S1 * (1.f / 16384.f);
        const float r1  = rsqrtf(Q1 * (1.f / 16384.f) - mu1 * mu1 + EPSF);
        const float mu2 = S2 * (1.f / 16384.f);
        const float r2  = rsqrtf(Q2 * (1.f / 16384.f) - mu2 * mu2 + EPSF);
        const float gw = __ldg(gnw + tid);
        k1s[tid] = a * gw * r1;
        k2s[tid] = a * gw * r2;
        cpart[tid] = a * (2.f * gbsh[tid] - gw * (mu1 * r1 + mu2 * r2));
    }
    __syncthreads();
    if (tid == 0) {
        float s = 0.f;
        #pragma unroll
        for (int i = 0; i < 16; i++) s += cpart[i];
        Csm = s;
    }
    // fold k1/k2 into the i-side silu tables (j-side stays unscaled)
    for (int idx = tid; idx < 2048; idx += 512) {
        const int c = idx >> 7, i = idx & 127;
        s1[c * 256 + i] *= k1s[c];
        s2[c * 256 + i] *= k2s[c];
    }
    __syncthreads();

    // ================= C: wts + gate + output (ascending, evict-first consumption) =======
    {
        const int rloc = tid >> 5;              // 0..15 rows per sub-iteration
        const float Cc = Csm;
        #pragma unroll 1
        for (int s = 0; s < 8; s++) {
            const int i = s * 16 + rloc;
            float4 v[16];
            float4 w4 = make_float4(Cc, Cc, Cc, Cc);
            #pragma unroll
            for (int c = 0; c < 16; c++) {
                v[c] = __ldcs((const float4*)(xb + c * HWPX + i * 128) + lane);
                const float a1 = s1[c * 256 + i];
                const float a2 = s2[c * 256 + i];
                const float4 j1 = *(const float4*)(s1 + c * 256 + 128 + 4 * lane);
                const float4 j2 = *(const float4*)(s2 + c * 256 + 128 + 4 * lane);
                w4.x += v[c].x * fmaf(a1, j1.x, a2 * j2.x);
                w4.y += v[c].y * fmaf(a1, j1.y, a2 * j2.y);
                w4.z += v[c].z * fmaf(a1, j1.z, a2 * j2.z);
                w4.w += v[c].w * fmaf(a1, j1.w, a2 * j2.w);
            }
            float4 sw;
            sw.x = siluf(w4.x); sw.y = siluf(w4.y); sw.z = siluf(w4.z); sw.w = siluf(w4.w);
            #pragma unroll
            for (int c = 0; c < 16; c++) {
                float4 o4;
                o4.x = v[c].x * sw.x; o4.y = v[c].y * sw.y;
                o4.z = v[c].z * sw.z; o4.w = v[c].w * sw.w;
                __stcs((float4*)(ob + c * HWPX + i * 128) + lane, o4);
            }
        }
    }
}

// ---------------- launch ----------------
extern "C" void kernel_launch(void* const* d_in, const int* in_sizes, int n_in,
                              void* d_out, int out_size) {
    const float* x    = (const float*)d_in[0];
    const float* w1   = (const float*)d_in[1];
    const float* b1   = (const float*)d_in[2];
    const float* w3   = (const float*)d_in[3];
    const float* b3   = (const float*)d_in[4];
    const float* gn_w = (const float*)d_in[5];
    const float* gn_b = (const float*)d_in[6];
    float* out = (float*)d_out;

    const int smem_bytes = (4096 + 4096 + 16 * 258) * (int)sizeof(float);  // 49280 B
    static bool attr_done = false;
    if (!attr_done) {
        cudaFuncSetAttribute(mega, cudaFuncAttributeMaxDynamicSharedMemorySize, smem_bytes);
        attr_done = true;
    }
    mega<<<128, 512, smem_bytes>>>(x, w1, b1, w3, b3, gn_w, gn_b, out);
}

// round 15
// speedup vs baseline: 1.1395x; 1.0004x over previous
#include <cuda_runtime.h>
#include <math.h>
#include <stdint.h>

#define HWPX 16384        // 128*128
#define EPSF 1e-5f

__device__ __forceinline__ float siluf(float v) { return v / (1.0f + __expf(-v)); }

// 256-bit cold read with L2 evict-last hint
__device__ __forceinline__ void ldg_el8(const float* p, float* v) {
    unsigned long long a, b, c, d;
    asm volatile("ld.global.nc.L2::evict_last.v4.b64 {%0,%1,%2,%3}, [%4];"
                 : "=l"(a), "=l"(b), "=l"(c), "=l"(d) : "l"(p));
    v[0] = __uint_as_float((unsigned)a); v[1] = __uint_as_float((unsigned)(a >> 32));
    v[2] = __uint_as_float((unsigned)b); v[3] = __uint_as_float((unsigned)(b >> 32));
    v[4] = __uint_as_float((unsigned)c); v[5] = __uint_as_float((unsigned)(c >> 32));
    v[6] = __uint_as_float((unsigned)d); v[7] = __uint_as_float((unsigned)(d >> 32));
}
// plain 256-bit read (L2-warm path)
__device__ __forceinline__ void ldg8(const float* p, float* v) {
    unsigned long long a, b, c, d;
    asm volatile("ld.global.nc.v4.b64 {%0,%1,%2,%3}, [%4];"
                 : "=l"(a), "=l"(b), "=l"(c), "=l"(d) : "l"(p));
    v[0] = __uint_as_float((unsigned)a); v[1] = __uint_as_float((unsigned)(a >> 32));
    v[2] = __uint_as_float((unsigned)b); v[3] = __uint_as_float((unsigned)(b >> 32));
    v[4] = __uint_as_float((unsigned)c); v[5] = __uint_as_float((unsigned)(c >> 32));
    v[6] = __uint_as_float((unsigned)d); v[7] = __uint_as_float((unsigned)(d >> 32));
}

// One block per bg-group (128 blocks, 512 threads). R14 structure; P1 AND P2
// use 256-bit loads (halved LDG issue); h^2 tables computed inline in kA.
__global__ __launch_bounds__(512, 1)
void mega(const float* __restrict__ x,
          const float* __restrict__ w1, const float* __restrict__ b1,
          const float* __restrict__ w3, const float* __restrict__ b3,
          const float* __restrict__ gnw, const float* __restrict__ gnb,
          float* __restrict__ out)
{
    extern __shared__ float sm[];
    float* s1  = sm;               // [16][256]
    float* s2  = sm + 4096;        // [16][256]
    float* hwb = sm + 8192;        // [16][258]  means+halo; aliased as h^2 tables after kA
    float* sq1 = sm + 8192;        // [16][128]
    float* sq2 = sm + 8192 + 2048; // [16][128]

    __shared__ float w1s[256], w3s[768], b1s[16], b3s[16];
    __shared__ float statv[64], k1s[16], k2s[16], cpart[16], gbsh[16];
    __shared__ float Csm;

    const int bg   = blockIdx.x;
    const int tid  = threadIdx.x;
    const int lane = tid & 31;
    const int wid  = tid >> 5;                   // 0..15 : one warp per channel
    const float* xb = x   + (size_t)bg * 16 * HWPX;
    float*       ob = out + (size_t)bg * 16 * HWPX;

    // ---- stage tiny weights ----
    if (tid < 256) w1s[tid] = __ldg(w1 + tid);
    for (int i2 = tid; i2 < 768; i2 += 512) w3s[i2] = __ldg(w3 + i2 * 3 + 1); // kw=1 column
    if (tid < 16) { b1s[tid] = __ldg(b1 + tid); b3s[tid] = __ldg(b3 + tid); gbsh[tid] = __ldg(gnb + tid); }

    // ================= P1: row + col means (pipelined, ascending, 256-bit evict_last) =====
    {
        const int c = wid;
        const float* g = xb + c * HWPX;
        float* hwc = hwb + c * 258;
        const int half = lane >> 4;              // 0/1
        const int seg  = lane & 15;
        const int colbase = seg * 8;
        float cs[8];
        #pragma unroll
        for (int j = 0; j < 8; j++) cs[j] = 0.f;
        float va[4][8], vb[4][8];

        #define P1_LOAD(BUF, I0)                                                   \
        {                                                                          \
            _Pragma("unroll")                                                      \
            for (int k = 0; k < 4; k++)                                            \
                ldg_el8(g + ((I0) + 2 * k + half) * 128 + colbase, BUF[k]);        \
        }
        #define P1_BODY(BUF, I0)                                                   \
        {                                                                          \
            _Pragma("unroll")                                                      \
            for (int k = 0; k < 4; k++) {                                          \
                float r = 0.f;                                                     \
                _Pragma("unroll")                                                  \
                for (int j = 0; j < 8; j++) { cs[j] += BUF[k][j]; r += BUF[k][j]; }\
                r += __shfl_xor_sync(0xffffffffu, r, 1);                           \
                r += __shfl_xor_sync(0xffffffffu, r, 2);                           \
                r += __shfl_xor_sync(0xffffffffu, r, 4);                           \
                r += __shfl_xor_sync(0xffffffffu, r, 8);                           \
                if (seg == 0) hwc[1 + (I0) + 2 * k + half] = r * (1.f / 128.f);    \
            }                                                                      \
        }

        P1_LOAD(va, 0)
        #pragma unroll 1
        for (int i0 = 0; i0 < 128; i0 += 16) {
            P1_LOAD(vb, i0 + 8)
            P1_BODY(va, i0)
            if (i0 + 16 < 128) P1_LOAD(va, i0 + 16)
            P1_BODY(vb, i0 + 8)
        }
        #undef P1_LOAD
        #undef P1_BODY

        #pragma unroll
        for (int j = 0; j < 8; j++) cs[j] += __shfl_xor_sync(0xffffffffu, cs[j], 16);
        if (half == 0) {
            #pragma unroll
            for (int j = 0; j < 8; j++)
                hwc[129 + colbase + j] = cs[j] * (1.f / 128.f);
        }
        if (lane == 0) { hwc[0] = 0.f; hwc[257] = 0.f; }   // conv halo
    }
    __syncthreads();

    // ================= kA: channel mix; h^2 tables inline for l<128 =================
    // NOTE: sq tables alias hwb, but each idx's hwb inputs (i*258 spans) are only
    // read here before any sq write to a DIFFERENT region? They alias! So compute
    // into registers first, write s1/s2, and defer sq writes until after a barrier
    // is NOT needed because sq region [8192, 12288) overlaps hwb [8192, 12320).
    // Safe approach: stage sq values in registers per-thread across the loop is
    // not possible (strided). Instead: keep original two-pass but fuse the squares
    // into the SAME loop via a second sweep guarded by one barrier (unchanged
    // semantics, one barrier saved by merging with the existing post-kA barrier).
    for (int idx = tid; idx < 4096; idx += 512) {
        const int o = idx >> 8, l = idx & 255;
        float a1 = b1s[o], a2 = b3s[o];
        #pragma unroll
        for (int i = 0; i < 16; i++) {
            const float* h = hwb + i * 258 + l;
            const float h0 = h[0], h1 = h[1], h2 = h[2];
            a1 = fmaf(w1s[o * 16 + i], h1, a1);
            const int wb = (o * 16 + i) * 3;
            a2 = fmaf(w3s[wb], h0, fmaf(w3s[wb + 1], h1, fmaf(w3s[wb + 2], h2, a2)));
        }
        s1[o * 256 + l] = siluf(a1);
        s2[o * 256 + l] = siluf(a2);
    }
    __syncthreads();
    for (int idx = tid; idx < 2048; idx += 512) {
        const int c = idx >> 7, i = idx & 127;
        const float a = s1[c * 256 + i];
        const float b = s2[c * 256 + i];
        sq1[idx] = a * a;
        sq2[idx] = b * b;
    }
    __syncthreads();

    // ================= P2: separable moments (pipelined, descending, 256-bit) ========
    {
        const int c = wid;
        const float* g = xb + c * HWPX;
        const int half = lane >> 4;              // 0/1: row parity within pair
        const int seg  = lane & 15;
        const int colbase = seg * 8;
        float wa8[8], wb8[8], wa2[8], wb2[8];
        #pragma unroll
        for (int j = 0; j < 8; j++) {
            wa8[j] = s1[c * 256 + 128 + colbase + j];
            wb8[j] = s2[c * 256 + 128 + colbase + j];
            wa2[j] = wa8[j] * wa8[j];
            wb2[j] = wb8[j] * wb8[j];
        }
        float sa = 0.f, qa = 0.f, sb = 0.f, qb = 0.f;
        float va[4][8], vb[4][8];

        #define P2_LOAD(BUF, I0)                                                   \
        {                                                                          \
            _Pragma("unroll")                                                      \
            for (int k = 0; k < 4; k++)                                            \
                ldg8(g + ((I0) + 2 * k + half) * 128 + colbase, BUF[k]);           \
        }
        #define P2_BODY(BUF, I0)                                                   \
        {                                                                          \
            _Pragma("unroll")                                                      \
            for (int k = 0; k < 4; k++) {                                          \
                const int i = (I0) + 2 * k + half;                                 \
                const float h1  = s1[c * 256 + i];                                 \
                const float h2  = s2[c * 256 + i];                                 \
                const float h1q = sq1[c * 128 + i];                                \
                const float h2q = sq2[c * 128 + i];                                \
                float d1 = 0.f, e1 = 0.f, d2 = 0.f, e2 = 0.f;                      \
                _Pragma("unroll")                                                  \
                for (int j = 0; j < 8; j++) {                                      \
                    const float v = BUF[k][j];                                     \
                    const float v2 = v * v;                                        \
                    d1 = fmaf(v, wa8[j], d1);                                      \
                    e1 = fmaf(v2, wa2[j], e1);                                     \
                    d2 = fmaf(v, wb8[j], d2);                                      \
                    e2 = fmaf(v2, wb2[j], e2);                                     \
                }                                                                  \
                sa = fmaf(h1, d1, sa);                                             \
                qa = fmaf(h1q, e1, qa);                                            \
                sb = fmaf(h2, d2, sb);                                             \
                qb = fmaf(h2q, e2, qb);                                            \
            }                                                                      \
        }

        P2_LOAD(va, 120)
        #pragma unroll 1
        for (int i0 = 120; i0 >= 0; i0 -= 16) {
            P2_LOAD(vb, i0 - 8)
            P2_BODY(va, i0)
            if (i0 - 16 >= 0) P2_LOAD(va, i0 - 16)
            P2_BODY(vb, i0 - 8)
        }
        #undef P2_LOAD
        #undef P2_BODY

        #pragma unroll
        for (int off = 16; off; off >>= 1) {
            sa += __shfl_down_sync(0xffffffffu, sa, off);
            qa += __shfl_down_sync(0xffffffffu, qa, off);
            sb += __shfl_down_sync(0xffffffffu, sb, off);
            qb += __shfl_down_sync(0xffffffffu, qb, off);
        }
        if (lane == 0) { statv[c * 4] = sa; statv[c * 4 + 1] = qa; statv[c * 4 + 2] = sb; statv[c * 4 + 3] = qb; }
    }
    __syncthreads();

    // ================= kB: scalars =================
    if (tid < 16) {
        float m = -1e30f;
        #pragma unroll
        for (int i = 0; i < 16; i++) m = fmaxf(m, gbsh[i]);
        float se = 0.f;
        #pragma unroll
        for (int i = 0; i < 16; i++) se += __expf(gbsh[i] - m);
        const float a = __expf(gbsh[tid] - m) / se;        // a1 == a2 == softmax(gn_b)
        const float S1 = statv[tid * 4], Q1 = statv[tid * 4 + 1];
        const float S2 = statv[tid * 4 + 2], Q2 = statv[tid * 4 + 3];
        const float mu1 = S1 * (1.f / 16384.f);
        const float r1  = rsqrtf(Q1 * (1.f / 16384.f) - mu1 * mu1 + EPSF);
        const float mu2 = S2 * (1.f / 16384.f);
        const float r2  = rsqrtf(Q2 * (1.f / 16384.f) - mu2 * mu2 + EPSF);
        const float gw = __ldg(gnw + tid);
        k1s[tid] = a * gw * r1;
        k2s[tid] = a * gw * r2;
        cpart[tid] = a * (2.f * gbsh[tid] - gw * (mu1 * r1 + mu2 * r2));
    }
    __syncthreads();
    if (tid == 0) {
        float s = 0.f;
        #pragma unroll
        for (int i = 0; i < 16; i++) s += cpart[i];
        Csm = s;
    }
    // fold k1/k2 into the i-side silu tables (j-side stays unscaled)
    for (int idx = tid; idx < 2048; idx += 512) {
        const int c = idx >> 7, i = idx & 127;
        s1[c * 256 + i] *= k1s[c];
        s2[c * 256 + i] *= k2s[c];
    }
    __syncthreads();

    // ================= C: wts + gate + output (ascending, x read once) =================
    {
        const int rloc = tid >> 5;              // 0..15 rows per sub-iteration
        const float Cc = Csm;
        #pragma unroll 1
        for (int s = 0; s < 8; s++) {
            const int i = s * 16 + rloc;
            float4 v[16];
            float4 w4 = make_float4(Cc, Cc, Cc, Cc);
            #pragma unroll
            for (int c = 0; c < 16; c++) {
                v[c] = __ldcs((const float4*)(xb + c * HWPX + i * 128) + lane);
                const float a1 = s1[c * 256 + i];
                const float a2 = s2[c * 256 + i];
                const float4 j1 = *(const float4*)(s1 + c * 256 + 128 + 4 * lane);
                const float4 j2 = *(const float4*)(s2 + c * 256 + 128 + 4 * lane);
                w4.x += v[c].x * fmaf(a1, j1.x, a2 * j2.x);
                w4.y += v[c].y * fmaf(a1, j1.y, a2 * j2.y);
                w4.z += v[c].z * fmaf(a1, j1.z, a2 * j2.z);
                w4.w += v[c].w * fmaf(a1, j1.w, a2 * j2.w);
            }
            float4 sw;
            sw.x = siluf(w4.x); sw.y = siluf(w4.y); sw.z = siluf(w4.z); sw.w = siluf(w4.w);
            #pragma unroll
            for (int c = 0; c < 16; c++) {
                float4 o4;
                o4.x = v[c].x * sw.x; o4.y = v[c].y * sw.y;
                o4.z = v[c].z * sw.z; o4.w = v[c].w * sw.w;
                __stcs((float4*)(ob + c * HWPX + i * 128) + lane, o4);
            }
        }
    }
}

// ---------------- launch ----------------
extern "C" void kernel_launch(void* const* d_in, const int* in_sizes, int n_in,
                              void* d_out, int out_size) {
    const float* x    = (const float*)d_in[0];
    const float* w1   = (const float*)d_in[1];
    const float* b1   = (const float*)d_in[2];
    const float* w3   = (const float*)d_in[3];
    const float* b3   = (const float*)d_in[4];
    const float* gn_w = (const float*)d_in[5];
    const float* gn_b = (const float*)d_in[6];
    float* out = (float*)d_out;

    const int smem_bytes = (4096 + 4096 + 16 * 258) * (int)sizeof(float);  // 49280 B
    static bool attr_done = false;
    if (!attr_done) {
        cudaFuncSetAttribute(mega, cudaFuncAttributeMaxDynamicSharedMemorySize, smem_bytes);
        attr_done = true;
    }
    mega<<<128, 512, smem_bytes>>>(x, w1, b1, w3, b3, gn_w, gn_b, out);
}

// round 16
// speedup vs baseline: 1.1654x; 1.0227x over previous
#include <cuda_runtime.h>
#include <math.h>
#include <stdint.h>

#define HWPX 16384        // 128*128
#define EPSF 1e-5f
#define NCACHE 2          // channels 14,15 cached in smem

__device__ __forceinline__ float siluf(float v) { return v / (1.0f + __expf(-v)); }

// 256-bit cold read with L2 evict-last hint (channels that will be re-read from L2)
__device__ __forceinline__ void ldg_el8(const float* p, float* v) {
    unsigned long long a, b, c, d;
    asm volatile("ld.global.nc.L2::evict_last.v4.b64 {%0,%1,%2,%3}, [%4];"
                 : "=l"(a), "=l"(b), "=l"(c), "=l"(d) : "l"(p));
    v[0] = __uint_as_float((unsigned)a); v[1] = __uint_as_float((unsigned)(a >> 32));
    v[2] = __uint_as_float((unsigned)b); v[3] = __uint_as_float((unsigned)(b >> 32));
    v[4] = __uint_as_float((unsigned)c); v[5] = __uint_as_float((unsigned)(c >> 32));
    v[6] = __uint_as_float((unsigned)d); v[7] = __uint_as_float((unsigned)(d >> 32));
}
// plain 256-bit read (L2-warm path)
__device__ __forceinline__ void ldg8(const float* p, float* v) {
    unsigned long long a, b, c, d;
    asm volatile("ld.global.nc.v4.b64 {%0,%1,%2,%3}, [%4];"
                 : "=l"(a), "=l"(b), "=l"(c), "=l"(d) : "l"(p));
    v[0] = __uint_as_float((unsigned)a); v[1] = __uint_as_float((unsigned)(a >> 32));
    v[2] = __uint_as_float((unsigned)b); v[3] = __uint_as_float((unsigned)(b >> 32));
    v[4] = __uint_as_float((unsigned)c); v[5] = __uint_as_float((unsigned)(c >> 32));
    v[6] = __uint_as_float((unsigned)d); v[7] = __uint_as_float((unsigned)(d >> 32));
}
// evict-first cold read for smem-cached channels (2x float4; no L2 residency wanted)
__device__ __forceinline__ void ldg8_cs(const float* p, float* v) {
    const float4 u0 = __ldcs((const float4*)p);
    const float4 u1 = __ldcs((const float4*)p + 1);
    v[0] = u0.x; v[1] = u0.y; v[2] = u0.z; v[3] = u0.w;
    v[4] = u1.x; v[5] = u1.y; v[6] = u1.z; v[7] = u1.w;
}

// One block per bg-group (128 blocks, 512 threads). R15 structure; channels
// 14-15 of each group's x are cached in smem during P1 (evict-first loads),
// shrinking the L2 working set for x to 112 MB < L2 capacity, so channels
// 0-13's P2/C re-reads stay L2-resident.
__global__ __launch_bounds__(512, 1)
void mega(const float* __restrict__ x,
          const float* __restrict__ w1, const float* __restrict__ b1,
          const float* __restrict__ w3, const float* __restrict__ b3,
          const float* __restrict__ gnw, const float* __restrict__ gnb,
          float* __restrict__ out)
{
    extern __shared__ float sm[];
    float* s1  = sm;               // [16][256]
    float* s2  = sm + 4096;        // [16][256]
    float* hwb = sm + 8192;        // [16][258]  means+halo; aliased as h^2 tables after kA
    float* sq1 = sm + 8192;        // [16][128]
    float* sq2 = sm + 8192 + 2048; // [16][128]
    float* xcache = sm + 12320;    // [2][16384] channels 14,15 of this group's x

    __shared__ float w1s[256], w3s[768], b1s[16], b3s[16];
    __shared__ float statv[64], k1s[16], k2s[16], cpart[16], gbsh[16];
    __shared__ float Csm;

    const int bg   = blockIdx.x;
    const int tid  = threadIdx.x;
    const int lane = tid & 31;
    const int wid  = tid >> 5;                   // 0..15 : one warp per channel
    const float* xb = x   + (size_t)bg * 16 * HWPX;
    float*       ob = out + (size_t)bg * 16 * HWPX;

    // ---- stage tiny weights ----
    if (tid < 256) w1s[tid] = __ldg(w1 + tid);
    for (int i2 = tid; i2 < 768; i2 += 512) w3s[i2] = __ldg(w3 + i2 * 3 + 1); // kw=1 column
    if (tid < 16) { b1s[tid] = __ldg(b1 + tid); b3s[tid] = __ldg(b3 + tid); gbsh[tid] = __ldg(gnb + tid); }

    // ================= P1: row + col means (pipelined, ascending, 256-bit) =====
    {
        const int c = wid;
        const float* g = xb + c * HWPX;
        float* hwc = hwb + c * 258;
        float* xcw = xcache + (c - 14) * HWPX;   // valid only for c >= 14
        const int half = lane >> 4;              // 0/1
        const int seg  = lane & 15;
        const int colbase = seg * 8;
        float cs[8];
        #pragma unroll
        for (int j = 0; j < 8; j++) cs[j] = 0.f;
        float va[4][8], vb[4][8];

        #define P1_LOAD(LOADFN, BUF, I0)                                           \
        {                                                                          \
            _Pragma("unroll")                                                      \
            for (int k = 0; k < 4; k++)                                            \
                LOADFN(g + ((I0) + 2 * k + half) * 128 + colbase, BUF[k]);         \
        }
        #define P1_BODY(BUF, I0, DO_CACHE)                                         \
        {                                                                          \
            _Pragma("unroll")                                                      \
            for (int k = 0; k < 4; k++) {                                          \
                const int row = (I0) + 2 * k + half;                               \
                if (DO_CACHE) {                                                    \
                    *(float4*)(xcw + row * 128 + colbase)     = *(float4*)&BUF[k][0]; \
                    *(float4*)(xcw + row * 128 + colbase + 4) = *(float4*)&BUF[k][4]; \
                }                                                                  \
                float r = 0.f;                                                     \
                _Pragma("unroll")                                                  \
                for (int j = 0; j < 8; j++) { cs[j] += BUF[k][j]; r += BUF[k][j]; }\
                r += __shfl_xor_sync(0xffffffffu, r, 1);                           \
                r += __shfl_xor_sync(0xffffffffu, r, 2);                           \
                r += __shfl_xor_sync(0xffffffffu, r, 4);                           \
                r += __shfl_xor_sync(0xffffffffu, r, 8);                           \
                if (seg == 0) hwc[1 + row] = r * (1.f / 128.f);                    \
            }                                                                      \
        }

        if (c < 16 - NCACHE) {
            P1_LOAD(ldg_el8, va, 0)
            #pragma unroll 1
            for (int i0 = 0; i0 < 128; i0 += 16) {
                P1_LOAD(ldg_el8, vb, i0 + 8)
                P1_BODY(va, i0, 0)
                if (i0 + 16 < 128) P1_LOAD(ldg_el8, va, i0 + 16)
                P1_BODY(vb, i0 + 8, 0)
            }
        } else {
            P1_LOAD(ldg8_cs, va, 0)
            #pragma unroll 1
            for (int i0 = 0; i0 < 128; i0 += 16) {
                P1_LOAD(ldg8_cs, vb, i0 + 8)
                P1_BODY(va, i0, 1)
                if (i0 + 16 < 128) P1_LOAD(ldg8_cs, va, i0 + 16)
                P1_BODY(vb, i0 + 8, 1)
            }
        }
        #undef P1_LOAD
        #undef P1_BODY

        #pragma unroll
        for (int j = 0; j < 8; j++) cs[j] += __shfl_xor_sync(0xffffffffu, cs[j], 16);
        if (half == 0) {
            #pragma unroll
            for (int j = 0; j < 8; j++)
                hwc[129 + colbase + j] = cs[j] * (1.f / 128.f);
        }
        if (lane == 0) { hwc[0] = 0.f; hwc[257] = 0.f; }   // conv halo
    }
    __syncthreads();

    // ================= kA: channel mix over concat length 256 =================
    for (int idx = tid; idx < 4096; idx += 512) {
        const int o = idx >> 8, l = idx & 255;
        float a1 = b1s[o], a2 = b3s[o];
        #pragma unroll
        for (int i = 0; i < 16; i++) {
            const float* h = hwb + i * 258 + l;
            const float h0 = h[0], h1 = h[1], h2 = h[2];
            a1 = fmaf(w1s[o * 16 + i], h1, a1);
            const int wb = (o * 16 + i) * 3;
            a2 = fmaf(w3s[wb], h0, fmaf(w3s[wb + 1], h1, fmaf(w3s[wb + 2], h2, a2)));
        }
        s1[o * 256 + l] = siluf(a1);
        s2[o * 256 + l] = siluf(a2);
    }
    __syncthreads();
    // h^2 tables (into dead hwb region)
    for (int idx = tid; idx < 2048; idx += 512) {
        const int c = idx >> 7, i = idx & 127;
        const float a = s1[c * 256 + i];
        const float b = s2[c * 256 + i];
        sq1[idx] = a * a;
        sq2[idx] = b * b;
    }
    __syncthreads();

    // ================= P2: separable moments (descending; smem path for cached) ========
    {
        const int c = wid;
        const float* g = xb + c * HWPX;
        const int half = lane >> 4;
        const int seg  = lane & 15;
        const int colbase = seg * 8;
        float wa8[8], wb8[8], wa2[8], wb2[8];
        #pragma unroll
        for (int j = 0; j < 8; j++) {
            wa8[j] = s1[c * 256 + 128 + colbase + j];
            wb8[j] = s2[c * 256 + 128 + colbase + j];
            wa2[j] = wa8[j] * wa8[j];
            wb2[j] = wb8[j] * wb8[j];
        }
        float sa = 0.f, qa = 0.f, sb = 0.f, qb = 0.f;

        #define P2_ACC(VPTR, I)                                                    \
        {                                                                          \
            const float h1  = s1[c * 256 + (I)];                                   \
            const float h2  = s2[c * 256 + (I)];                                   \
            const float h1q = sq1[c * 128 + (I)];                                  \
            const float h2q = sq2[c * 128 + (I)];                                  \
            float d1 = 0.f, e1 = 0.f, d2 = 0.f, e2 = 0.f;                          \
            _Pragma("unroll")                                                      \
            for (int j = 0; j < 8; j++) {                                          \
                const float v = (VPTR)[j];                                         \
                const float v2 = v * v;                                            \
                d1 = fmaf(v, wa8[j], d1);                                          \
                e1 = fmaf(v2, wa2[j], e1);                                         \
                d2 = fmaf(v, wb8[j], d2);                                          \
                e2 = fmaf(v2, wb2[j], e2);                                         \
            }                                                                      \
            sa = fmaf(h1, d1, sa);                                                 \
            qa = fmaf(h1q, e1, qa);                                                \
            sb = fmaf(h2, d2, sb);                                                 \
            qb = fmaf(h2q, e2, qb);                                                \
        }

        if (c < 16 - NCACHE) {
            float va[4][8], vb[4][8];
            #define P2_LOAD(BUF, I0)                                               \
            {                                                                      \
                _Pragma("unroll")                                                  \
                for (int k = 0; k < 4; k++)                                        \
                    ldg8(g + ((I0) + 2 * k + half) * 128 + colbase, BUF[k]);       \
            }
            #define P2_BODY(BUF, I0)                                               \
            {                                                                      \
                _Pragma("unroll")                                                  \
                for (int k = 0; k < 4; k++) { P2_ACC(BUF[k], (I0) + 2 * k + half) }\
            }
            P2_LOAD(va, 120)
            #pragma unroll 1
            for (int i0 = 120; i0 >= 0; i0 -= 16) {
                P2_LOAD(vb, i0 - 8)
                P2_BODY(va, i0)
                if (i0 - 16 >= 0) P2_LOAD(va, i0 - 16)
                P2_BODY(vb, i0 - 8)
            }
            #undef P2_LOAD
            #undef P2_BODY
        } else {
            const float* xcw = xcache + (c - 14) * HWPX;
            #pragma unroll 1
            for (int i0 = 0; i0 < 128; i0 += 8) {
                #pragma unroll
                for (int k = 0; k < 4; k++) {
                    const int i = i0 + 2 * k + half;
                    const float* p = xcw + i * 128 + colbase;
                    float vv[8];
                    const float4 u0 = *(const float4*)p;
                    const float4 u1 = *(const float4*)(p + 4);
                    vv[0] = u0.x; vv[1] = u0.y; vv[2] = u0.z; vv[3] = u0.w;
                    vv[4] = u1.x; vv[5] = u1.y; vv[6] = u1.z; vv[7] = u1.w;
                    P2_ACC(vv, i)
                }
            }
        }
        #undef P2_ACC

        #pragma unroll
        for (int off = 16; off; off >>= 1) {
            sa += __shfl_down_sync(0xffffffffu, sa, off);
            qa += __shfl_down_sync(0xffffffffu, qa, off);
            sb += __shfl_down_sync(0xffffffffu, sb, off);
            qb += __shfl_down_sync(0xffffffffu, qb, off);
        }
        if (lane == 0) { statv[c * 4] = sa; statv[c * 4 + 1] = qa; statv[c * 4 + 2] = sb; statv[c * 4 + 3] = qb; }
    }
    __syncthreads();

    // ================= kB: scalars =================
    if (tid < 16) {
        float m = -1e30f;
        #pragma unroll
        for (int i = 0; i < 16; i++) m = fmaxf(m, gbsh[i]);
        float se = 0.f;
        #pragma unroll
        for (int i = 0; i < 16; i++) se += __expf(gbsh[i] - m);
        const float a = __expf(gbsh[tid] - m) / se;        // a1 == a2 == softmax(gn_b)
        const float S1 = statv[tid * 4], Q1 = statv[tid * 4 + 1];
        const float S2 = statv[tid * 4 + 2], Q2 = statv[tid * 4 + 3];
        const float mu1 = S1 * (1.f / 16384.f);
        const float r1  = rsqrtf(Q1 * (1.f / 16384.f) - mu1 * mu1 + EPSF);
        const float mu2 = S2 * (1.f / 16384.f);
        const float r2  = rsqrtf(Q2 * (1.f / 16384.f) - mu2 * mu2 + EPSF);
        const float gw = __ldg(gnw + tid);
        k1s[tid] = a * gw * r1;
        k2s[tid] = a * gw * r2;
        cpart[tid] = a * (2.f * gbsh[tid] - gw * (mu1 * r1 + mu2 * r2));
    }
    __syncthreads();
    if (tid == 0) {
        float s = 0.f;
        #pragma unroll
        for (int i = 0; i < 16; i++) s += cpart[i];
        Csm = s;
    }
    // fold k1/k2 into the i-side silu tables (j-side stays unscaled)
    for (int idx = tid; idx < 2048; idx += 512) {
        const int c = idx >> 7, i = idx & 127;
        s1[c * 256 + i] *= k1s[c];
        s2[c * 256 + i] *= k2s[c];
    }
    __syncthreads();

    // ================= C: wts + gate + output (ascending; cached ch from smem) =========
    {
        const int rloc = tid >> 5;              // 0..15 rows per sub-iteration
        const float Cc = Csm;
        #pragma unroll 1
        for (int s = 0; s < 8; s++) {
            const int i = s * 16 + rloc;
            float4 v[16];
            float4 w4 = make_float4(Cc, Cc, Cc, Cc);
            #pragma unroll
            for (int c = 0; c < 16; c++) {
                if (c < 16 - NCACHE)
                    v[c] = __ldcs((const float4*)(xb + c * HWPX + i * 128) + lane);
                else
                    v[c] = *((const float4*)(xcache + (c - 14) * HWPX + i * 128) + lane);
                const float a1 = s1[c * 256 + i];
                const float a2 = s2[c * 256 + i];
                const float4 j1 = *(const float4*)(s1 + c * 256 + 128 + 4 * lane);
                const float4 j2 = *(const float4*)(s2 + c * 256 + 128 + 4 * lane);
                w4.x += v[c].x * fmaf(a1, j1.x, a2 * j2.x);
                w4.y += v[c].y * fmaf(a1, j1.y, a2 * j2.y);
                w4.z += v[c].z * fmaf(a1, j1.z, a2 * j2.z);
                w4.w += v[c].w * fmaf(a1, j1.w, a2 * j2.w);
            }
            float4 sw;
            sw.x = siluf(w4.x); sw.y = siluf(w4.y); sw.z = siluf(w4.z); sw.w = siluf(w4.w);
            #pragma unroll
            for (int c = 0; c < 16; c++) {
                float4 o4;
                o4.x = v[c].x * sw.x; o4.y = v[c].y * sw.y;
                o4.z = v[c].z * sw.z; o4.w = v[c].w * sw.w;
                __stcs((float4*)(ob + c * HWPX + i * 128) + lane, o4);
            }
        }
    }
}

// ---------------- launch ----------------
extern "C" void kernel_launch(void* const* d_in, const int* in_sizes, int n_in,
                              void* d_out, int out_size) {
    const float* x    = (const float*)d_in[0];
    const float* w1   = (const float*)d_in[1];
    const float* b1   = (const float*)d_in[2];
    const float* w3   = (const float*)d_in[3];
    const float* b3   = (const float*)d_in[4];
    const float* gn_w = (const float*)d_in[5];
    const float* gn_b = (const float*)d_in[6];
    float* out = (float*)d_out;

    // s1 4096 + s2 4096 + hwb 4128 + xcache 32768 = 45088 floats = 180352 B
    const int smem_bytes = 45088 * (int)sizeof(float);
    static bool attr_done = false;
    if (!attr_done) {
        cudaFuncSetAttribute(mega, cudaFuncAttributeMaxDynamicSharedMemorySize, smem_bytes);
        attr_done = true;
    }
    mega<<<128, 512, smem_bytes>>>(x, w1, b1, w3, b3, gn_w, gn_b, out);
}